// round 1
// baseline (speedup 1.0000x reference)
#include <cuda_runtime.h>
#include <cuda_bf16.h>

#define BATCH 16
#define NN 2048
#define DD 256

// Scratch (no allocations allowed): M = W@W^T, G = X@M
__device__ float d_M[DD * DD];
__device__ float d_G[BATCH * NN * DD];

// ---------------------------------------------------------------------------
// Kernel 1: M = W @ W^T   (256x256x256, trivial)
// ---------------------------------------------------------------------------
__global__ void wwt_kernel(const float* __restrict__ W) {
    __shared__ float sR[16][257];
    __shared__ float sC[16][257];
    int tx = threadIdx.x, ty = threadIdx.y;
    int t = ty * 16 + tx;
    int r0 = blockIdx.y * 16, c0 = blockIdx.x * 16;
    {
        int row = t >> 4;
        int base = t & 15;
#pragma unroll
        for (int p = 0; p < 16; ++p) {
            int col = base + p * 16;
            sR[row][col] = W[(r0 + row) * DD + col];
            sC[row][col] = W[(c0 + row) * DD + col];
        }
    }
    __syncthreads();
    float acc = 0.f;
#pragma unroll 8
    for (int k = 0; k < DD; ++k) acc += sR[ty][k] * sC[tx][k];
    d_M[(r0 + ty) * DD + (c0 + tx)] = acc;
}

// ---------------------------------------------------------------------------
// Kernel 2: G = X @ M   (32768 x 256 x 256), 64x64 tiles, 4x4 micro
// ---------------------------------------------------------------------------
__global__ __launch_bounds__(256) void gproj_kernel(const float* __restrict__ X) {
    __shared__ float sA[64 * 68];
    __shared__ float sB[64 * 68];
    int t = threadIdx.x;
    int tx = t & 15, ty = t >> 4;
    int row0 = blockIdx.y * 64;
    int col0 = blockIdx.x * 64;

    float acc[4][4];
#pragma unroll
    for (int i = 0; i < 4; ++i)
#pragma unroll
        for (int j = 0; j < 4; ++j) acc[i][j] = 0.f;

    for (int kc = 0; kc < 4; ++kc) {
        // load 64x64 A chunk and 64x64 B chunk
#pragma unroll
        for (int p = 0; p < 4; ++p) {
            int r = p * 16 + (t >> 4);
            int c4 = (t & 15);
            float4 va = *(const float4*)&X[(row0 + r) * DD + kc * 64 + c4 * 4];
            *(float4*)&sA[r * 68 + c4 * 4] = va;
            float4 vb = *(const float4*)&d_M[(kc * 64 + r) * DD + col0 + c4 * 4];
            *(float4*)&sB[r * 68 + c4 * 4] = vb;
        }
        __syncthreads();
#pragma unroll
        for (int k4 = 0; k4 < 16; ++k4) {
            float a[4][4], b[4][4];
#pragma unroll
            for (int i = 0; i < 4; ++i) {
                float4 v = *(float4*)&sA[(ty * 4 + i) * 68 + k4 * 4];
                a[i][0] = v.x; a[i][1] = v.y; a[i][2] = v.z; a[i][3] = v.w;
            }
#pragma unroll
            for (int kk = 0; kk < 4; ++kk) {
                float4 v = *(float4*)&sB[(k4 * 4 + kk) * 68 + tx * 4];
                b[kk][0] = v.x; b[kk][1] = v.y; b[kk][2] = v.z; b[kk][3] = v.w;
            }
#pragma unroll
            for (int i = 0; i < 4; ++i)
#pragma unroll
                for (int kk = 0; kk < 4; ++kk)
#pragma unroll
                    for (int j = 0; j < 4; ++j)
                        acc[i][j] += a[i][kk] * b[kk][j];
        }
        __syncthreads();
    }
#pragma unroll
    for (int i = 0; i < 4; ++i) {
        float4 v = make_float4(acc[i][0], acc[i][1], acc[i][2], acc[i][3]);
        *(float4*)&d_G[(row0 + ty * 4 + i) * DD + col0 + tx * 4] = v;
    }
}

// ---------------------------------------------------------------------------
// Kernel 3: fused flash-style attention.
//   per CTA: 32 query rows of one batch. Loop over 32 m-tiles of 64.
//   S = G_tile @ X_tile^T ; leaky 0.2 ; * adj ; online softmax ; O += P @ X_tile
// Thread layout: 256 threads = (ty 0..15) x (tx 0..15); each thread owns
// rows r0=2*ty..+1, S-cols c0=4*tx..+3, O cols (chunk*64 + 4*tx ..+3).
// ---------------------------------------------------------------------------
__global__ __launch_bounds__(256, 2) void attn_kernel(
    const float* __restrict__ X, const float* __restrict__ ADJ,
    const float* __restrict__ bias, float* __restrict__ OUT) {
    extern __shared__ float sm[];
    float* sQ  = sm;                 // 32 x 260
    float* sKV = sm + 32 * 260;      // 64 x 68
    float* sP  = sKV + 64 * 68;      // 32 x 68

    int t = threadIdx.x;
    int tx = t & 15, ty = t >> 4;
    int b = blockIdx.y;
    int n0 = blockIdx.x * 32;
    int r0 = ty * 2;
    int c0 = tx * 4;

    // Load Q tile: G[b][n0..n0+31][0..255]
    {
        int r = t >> 3;
        int f8 = t & 7;
        const float* src = &d_G[(size_t)(b * NN + n0 + r) * DD];
#pragma unroll
        for (int p = 0; p < 8; ++p) {
            int c4 = p * 8 + f8;
            *(float4*)&sQ[r * 260 + c4 * 4] = *(const float4*)&src[c4 * 4];
        }
    }

    float O[2][16];
#pragma unroll
    for (int i = 0; i < 2; ++i)
#pragma unroll
        for (int j = 0; j < 16; ++j) O[i][j] = 0.f;
    float mrow[2] = {-1e30f, -1e30f};
    float lrow[2] = {0.f, 0.f};

    const float* Xb = &X[(size_t)b * NN * DD];
    __syncthreads();

    for (int mt = 0; mt < 32; ++mt) {
        int m0 = mt * 64;
        float s[2][4] = {{0.f, 0.f, 0.f, 0.f}, {0.f, 0.f, 0.f, 0.f}};

        // ---- S = Q @ K^T over 4 k-chunks of 64 ----
        for (int kc = 0; kc < 4; ++kc) {
#pragma unroll
            for (int p = 0; p < 4; ++p) {
                int r = p * 16 + (t >> 4);
                int c4 = t & 15;
                *(float4*)&sKV[r * 68 + c4 * 4] =
                    *(const float4*)&Xb[(m0 + r) * DD + kc * 64 + c4 * 4];
            }
            __syncthreads();
#pragma unroll
            for (int k4 = 0; k4 < 16; ++k4) {
                float a0[4], a1[4], bb[4][4];
                {
                    float4 v = *(float4*)&sQ[r0 * 260 + kc * 64 + k4 * 4];
                    a0[0] = v.x; a0[1] = v.y; a0[2] = v.z; a0[3] = v.w;
                    v = *(float4*)&sQ[(r0 + 1) * 260 + kc * 64 + k4 * 4];
                    a1[0] = v.x; a1[1] = v.y; a1[2] = v.z; a1[3] = v.w;
                }
#pragma unroll
                for (int j = 0; j < 4; ++j) {
                    float4 v = *(float4*)&sKV[(c0 + j) * 68 + k4 * 4];
                    bb[j][0] = v.x; bb[j][1] = v.y; bb[j][2] = v.z; bb[j][3] = v.w;
                }
#pragma unroll
                for (int j = 0; j < 4; ++j)
#pragma unroll
                    for (int kk = 0; kk < 4; ++kk) {
                        s[0][j] += a0[kk] * bb[j][kk];
                        s[1][j] += a1[kk] * bb[j][kk];
                    }
            }
            __syncthreads();
        }

        // ---- leaky_relu(0.2) then * adj ----
        {
            const float* adjp = &ADJ[((size_t)(b * NN + n0 + r0)) * NN + m0 + c0];
            float4 av0 = *(const float4*)adjp;
            float4 av1 = *(const float4*)(adjp + NN);
            s[0][0] = fmaxf(s[0][0], 0.2f * s[0][0]) * av0.x;
            s[0][1] = fmaxf(s[0][1], 0.2f * s[0][1]) * av0.y;
            s[0][2] = fmaxf(s[0][2], 0.2f * s[0][2]) * av0.z;
            s[0][3] = fmaxf(s[0][3], 0.2f * s[0][3]) * av0.w;
            s[1][0] = fmaxf(s[1][0], 0.2f * s[1][0]) * av1.x;
            s[1][1] = fmaxf(s[1][1], 0.2f * s[1][1]) * av1.y;
            s[1][2] = fmaxf(s[1][2], 0.2f * s[1][2]) * av1.z;
            s[1][3] = fmaxf(s[1][3], 0.2f * s[1][3]) * av1.w;
        }

        // ---- online softmax update ----
        float rmax0 = fmaxf(fmaxf(s[0][0], s[0][1]), fmaxf(s[0][2], s[0][3]));
        float rmax1 = fmaxf(fmaxf(s[1][0], s[1][1]), fmaxf(s[1][2], s[1][3]));
#pragma unroll
        for (int off = 8; off >= 1; off >>= 1) {
            rmax0 = fmaxf(rmax0, __shfl_xor_sync(0xffffffffu, rmax0, off));
            rmax1 = fmaxf(rmax1, __shfl_xor_sync(0xffffffffu, rmax1, off));
        }
        float mnew0 = fmaxf(mrow[0], rmax0);
        float mnew1 = fmaxf(mrow[1], rmax1);
        float scale0 = __expf(mrow[0] - mnew0);
        float scale1 = __expf(mrow[1] - mnew1);
        float p0[4], p1[4];
#pragma unroll
        for (int j = 0; j < 4; ++j) {
            p0[j] = __expf(s[0][j] - mnew0);
            p1[j] = __expf(s[1][j] - mnew1);
        }
        float rs0 = p0[0] + p0[1] + p0[2] + p0[3];
        float rs1 = p1[0] + p1[1] + p1[2] + p1[3];
#pragma unroll
        for (int off = 8; off >= 1; off >>= 1) {
            rs0 += __shfl_xor_sync(0xffffffffu, rs0, off);
            rs1 += __shfl_xor_sync(0xffffffffu, rs1, off);
        }
        lrow[0] = lrow[0] * scale0 + rs0;
        lrow[1] = lrow[1] * scale1 + rs1;
        mrow[0] = mnew0;
        mrow[1] = mnew1;
#pragma unroll
        for (int j = 0; j < 16; ++j) {
            O[0][j] *= scale0;
            O[1][j] *= scale1;
        }
        *(float4*)&sP[r0 * 68 + c0] = make_float4(p0[0], p0[1], p0[2], p0[3]);
        *(float4*)&sP[(r0 + 1) * 68 + c0] = make_float4(p1[0], p1[1], p1[2], p1[3]);
        __syncthreads();

        // ---- O += P @ V over 4 d-chunks of 64 ----
        for (int dc = 0; dc < 4; ++dc) {
#pragma unroll
            for (int p = 0; p < 4; ++p) {
                int r = p * 16 + (t >> 4);
                int c4 = t & 15;
                *(float4*)&sKV[r * 68 + c4 * 4] =
                    *(const float4*)&Xb[(m0 + r) * DD + dc * 64 + c4 * 4];
            }
            __syncthreads();
#pragma unroll 8
            for (int kk = 0; kk < 64; ++kk) {
                float pa = sP[r0 * 68 + kk];
                float pb = sP[(r0 + 1) * 68 + kk];
                float4 v = *(float4*)&sKV[kk * 68 + tx * 4];
                O[0][dc * 4 + 0] += pa * v.x;
                O[0][dc * 4 + 1] += pa * v.y;
                O[0][dc * 4 + 2] += pa * v.z;
                O[0][dc * 4 + 3] += pa * v.w;
                O[1][dc * 4 + 0] += pb * v.x;
                O[1][dc * 4 + 1] += pb * v.y;
                O[1][dc * 4 + 2] += pb * v.z;
                O[1][dc * 4 + 3] += pb * v.w;
            }
            __syncthreads();
        }
    }

    // ---- epilogue: normalize, add bias, store ----
    float inv0 = 1.f / lrow[0];
    float inv1 = 1.f / lrow[1];
#pragma unroll
    for (int dc = 0; dc < 4; ++dc) {
        int col = dc * 64 + c0;
        float4 bv = *(const float4*)&bias[col];
        float4 o0 = make_float4(O[0][dc * 4 + 0] * inv0 + bv.x,
                                O[0][dc * 4 + 1] * inv0 + bv.y,
                                O[0][dc * 4 + 2] * inv0 + bv.z,
                                O[0][dc * 4 + 3] * inv0 + bv.w);
        float4 o1 = make_float4(O[1][dc * 4 + 0] * inv1 + bv.x,
                                O[1][dc * 4 + 1] * inv1 + bv.y,
                                O[1][dc * 4 + 2] * inv1 + bv.z,
                                O[1][dc * 4 + 3] * inv1 + bv.w);
        *(float4*)&OUT[(size_t)(b * NN + n0 + r0) * DD + col] = o0;
        *(float4*)&OUT[(size_t)(b * NN + n0 + r0 + 1) * DD + col] = o1;
    }
}

// ---------------------------------------------------------------------------
extern "C" void kernel_launch(void* const* d_in, const int* in_sizes, int n_in,
                              void* d_out, int out_size) {
    const float* x    = (const float*)d_in[0];  // [16,2048,256]
    const float* adj  = (const float*)d_in[1];  // [16,2048,2048]
    const float* W    = (const float*)d_in[2];  // [256,256]
    const float* bias = (const float*)d_in[3];  // [256]
    float* out = (float*)d_out;

    wwt_kernel<<<dim3(16, 16), dim3(16, 16)>>>(W);
    gproj_kernel<<<dim3(4, 512), 256>>>(x);

    const int smem_bytes = (32 * 260 + 64 * 68 + 32 * 68) * 4;  // 59392
    cudaFuncSetAttribute(attn_kernel, cudaFuncAttributeMaxDynamicSharedMemorySize,
                         smem_bytes);
    attn_kernel<<<dim3(64, 16), 256, smem_bytes>>>(x, adj, bias, out);
}

// round 3
// speedup vs baseline: 2.6804x; 2.6804x over previous
#include <cuda_runtime.h>
#include <cuda_bf16.h>
#include <cstdint>

#define BATCH 16
#define NN 2048
#define DD 256

// ---------------- scratch (static device globals; no allocs) ----------------
__device__ __nv_bfloat16 d_Mhi[DD * DD];
__device__ __nv_bfloat16 d_Mlo[DD * DD];
__device__ __nv_bfloat16 d_Ghi[BATCH * NN * DD];
__device__ __nv_bfloat16 d_Glo[BATCH * NN * DD];
__device__ __nv_bfloat16 d_Xhi[BATCH * NN * DD];
__device__ __nv_bfloat16 d_Xlo[BATCH * NN * DD];
__device__ __nv_bfloat16 d_Xthi[BATCH * DD * NN];
__device__ __nv_bfloat16 d_Xtlo[BATCH * DD * NN];
__device__ float d_S[(size_t)BATCH * NN * NN];   // 256 MiB score scratch
__device__ float d_pm[(size_t)BATCH * NN * 32];  // per-(row, 64col-seg) max
__device__ float d_pl[(size_t)BATCH * NN * 32];  // per-(row, 64col-seg) sumexp
__device__ float d_rm[BATCH * NN];
__device__ float d_rl[BATCH * NN];

// ---------------- helpers ----------------
__device__ __forceinline__ uint32_t smem_to_u32(const void* p) {
    uint32_t a;
    asm("{ .reg .u64 t; cvta.to.shared.u64 t, %1; cvt.u32.u64 %0, t; }" : "=r"(a) : "l"(p));
    return a;
}
__device__ __forceinline__ void split_hl(float v, float& h, float& l) {
    __nv_bfloat16 hb = __float2bfloat16(v);
    h = __bfloat162float(hb);
    l = v - h;
}
__device__ __forceinline__ uint32_t pack_bf2(float a, float b) {
    __nv_bfloat162 h = __floats2bfloat162_rn(a, b);
    return *(uint32_t*)&h;
}

// ldmatrix x4 (baseline PTX, allowed on sm_103)
__device__ __forceinline__ void ldmx4(uint32_t (&d)[4], uint32_t addr) {
    asm volatile("ldmatrix.sync.aligned.m8n8.x4.shared.b16 {%0,%1,%2,%3}, [%4];"
                 : "=r"(d[0]), "=r"(d[1]), "=r"(d[2]), "=r"(d[3]) : "r"(addr));
}
// bf16 mma with fp32 accum (baseline PTX, sm_80+)
__device__ __forceinline__ void mma16816(float (&c)[4], const uint32_t (&a)[4],
                                         uint32_t b0, uint32_t b1) {
    asm volatile(
        "mma.sync.aligned.m16n8k16.row.col.f32.bf16.bf16.f32 "
        "{%0,%1,%2,%3}, {%4,%5,%6,%7}, {%8,%9}, {%0,%1,%2,%3};"
        : "+f"(c[0]), "+f"(c[1]), "+f"(c[2]), "+f"(c[3])
        : "r"(a[0]), "r"(a[1]), "r"(a[2]), "r"(a[3]), "r"(b0), "r"(b1));
}

// Tiles in smem: rows of 64 bf16 = 128 bytes, SW128 swizzle.
// swizzled byte = byte ^ ((byte>>3)&0x70)  (XOR 16B-chunk idx by row%8)
__device__ __forceinline__ uint32_t swz(uint32_t byte) {
    return byte ^ ((byte >> 3) & 0x70);
}
// Stage a [rows x 64] bf16 chunk from gmem (row stride = stride elems).
__device__ __forceinline__ void stage64(char* dst, const __nv_bfloat16* src,
                                        int stride, int rows, int tid) {
    for (int i = tid; i < rows * 8; i += 256) {
        int r = i >> 3, c = i & 7;
        uint32_t byte = (uint32_t)(r * 128 + c * 16);
        *(uint4*)(dst + swz(byte)) = *(const uint4*)(src + (size_t)r * stride + c * 8);
    }
}
// ldmatrix address for one lane: 16x16 block at (rowbase, kbyte) of a tile.
__device__ __forceinline__ uint32_t tile_addr(uint32_t base, int rowbase, int kbyte, int lane) {
    int mat = lane >> 3, ri = lane & 7;
    int row = rowbase + (mat & 1) * 8 + ri;
    uint32_t byte = (uint32_t)(row * 128 + kbyte + (mat >> 1) * 16);
    return base + swz(byte);
}

// Warp computes 32x64 over one k=64 chunk, 3 passes (AhiBhi, AhiBlo, AloBhi).
__device__ __forceinline__ void mma_chunk3(float (&acc)[2][8][4],
                                           uint32_t aHi, uint32_t aLo,
                                           uint32_t bHi, uint32_t bLo,
                                           int mrow, int ncol, int lane) {
#pragma unroll
    for (int k16 = 0; k16 < 4; ++k16) {
        int kb = k16 * 32;
        uint32_t ah[2][4], bh[4][4];
        ldmx4(ah[0], tile_addr(aHi, mrow, kb, lane));
        ldmx4(ah[1], tile_addr(aHi, mrow + 16, kb, lane));
#pragma unroll
        for (int g = 0; g < 4; ++g) ldmx4(bh[g], tile_addr(bHi, ncol + g * 16, kb, lane));
#pragma unroll
        for (int mi = 0; mi < 2; ++mi)
#pragma unroll
            for (int g = 0; g < 4; ++g) {
                mma16816(acc[mi][g * 2 + 0], ah[mi], bh[g][0], bh[g][2]);
                mma16816(acc[mi][g * 2 + 1], ah[mi], bh[g][1], bh[g][3]);
            }
        {
            uint32_t bl[4][4];
#pragma unroll
            for (int g = 0; g < 4; ++g) ldmx4(bl[g], tile_addr(bLo, ncol + g * 16, kb, lane));
#pragma unroll
            for (int mi = 0; mi < 2; ++mi)
#pragma unroll
                for (int g = 0; g < 4; ++g) {
                    mma16816(acc[mi][g * 2 + 0], ah[mi], bl[g][0], bl[g][2]);
                    mma16816(acc[mi][g * 2 + 1], ah[mi], bl[g][1], bl[g][3]);
                }
        }
        {
            uint32_t al[2][4];
            ldmx4(al[0], tile_addr(aLo, mrow, kb, lane));
            ldmx4(al[1], tile_addr(aLo, mrow + 16, kb, lane));
#pragma unroll
            for (int mi = 0; mi < 2; ++mi)
#pragma unroll
                for (int g = 0; g < 4; ++g) {
                    mma16816(acc[mi][g * 2 + 0], al[mi], bh[g][0], bh[g][2]);
                    mma16816(acc[mi][g * 2 + 1], al[mi], bh[g][1], bh[g][3]);
                }
        }
    }
}

// ---------------------------------------------------------------------------
// K1: M = W @ W^T  -> hi/lo bf16
// ---------------------------------------------------------------------------
__global__ void wwt_kernel(const float* __restrict__ W) {
    __shared__ float sR[16][257];
    __shared__ float sC[16][257];
    int tx = threadIdx.x, ty = threadIdx.y;
    int t = ty * 16 + tx;
    int r0 = blockIdx.y * 16, c0 = blockIdx.x * 16;
    {
        int row = t >> 4, base = t & 15;
#pragma unroll
        for (int p = 0; p < 16; ++p) {
            int col = base + p * 16;
            sR[row][col] = W[(r0 + row) * DD + col];
            sC[row][col] = W[(c0 + row) * DD + col];
        }
    }
    __syncthreads();
    float acc = 0.f;
#pragma unroll 8
    for (int k = 0; k < DD; ++k) acc += sR[ty][k] * sC[tx][k];
    float h, l;
    split_hl(acc, h, l);
    d_Mhi[(r0 + ty) * DD + (c0 + tx)] = __float2bfloat16(h);
    d_Mlo[(r0 + ty) * DD + (c0 + tx)] = __float2bfloat16(l);
}

// ---------------------------------------------------------------------------
// K2: X -> Xhi/Xlo (row-major) + Xthi/Xtlo ([b][d][m])
// ---------------------------------------------------------------------------
__global__ __launch_bounds__(256) void convx_kernel(const float* __restrict__ X) {
    __shared__ float tile[32][33];
    int b = blockIdx.z;
    int m0 = blockIdx.y * 32, d0 = blockIdx.x * 32;
    int j = threadIdx.x & 31, i0 = threadIdx.x >> 5;
    const float* Xb = X + (size_t)b * NN * DD;
#pragma unroll
    for (int i = i0; i < 32; i += 8) {
        float v = Xb[(size_t)(m0 + i) * DD + d0 + j];
        tile[i][j] = v;
        float h, l;
        split_hl(v, h, l);
        size_t idx = (size_t)b * NN * DD + (size_t)(m0 + i) * DD + d0 + j;
        d_Xhi[idx] = __float2bfloat16(h);
        d_Xlo[idx] = __float2bfloat16(l);
    }
    __syncthreads();
#pragma unroll
    for (int i = i0; i < 32; i += 8) {
        float v = tile[j][i];   // = X[m0+j][d0+i]
        float h, l;
        split_hl(v, h, l);
        size_t idx = (size_t)b * DD * NN + (size_t)(d0 + i) * NN + m0 + j;
        d_Xthi[idx] = __float2bfloat16(h);
        d_Xtlo[idx] = __float2bfloat16(l);
    }
}

// ---------------------------------------------------------------------------
// K3: G = X @ M (mma).  grid (nh=2, tile=256).  A=Xhi/Xlo, B=Mhi/Mlo.
// ---------------------------------------------------------------------------
__global__ __launch_bounds__(256) void gproj_kernel() {
    extern __shared__ __align__(128) char sm[];
    uint32_t base = smem_to_u32(sm);
    int tid = threadIdx.x, lane = tid & 31, wid = tid >> 5;
    int nh = blockIdx.x, ti = blockIdx.y;
    int mrow = (wid >> 1) * 32, ncol = (wid & 1) * 64;

    float acc[2][8][4];
#pragma unroll
    for (int mi = 0; mi < 2; ++mi)
#pragma unroll
        for (int nf = 0; nf < 8; ++nf)
#pragma unroll
            for (int q = 0; q < 4; ++q) acc[mi][nf][q] = 0.f;

    const __nv_bfloat16* Ahi = d_Xhi + (size_t)ti * 128 * DD;
    const __nv_bfloat16* Alo = d_Xlo + (size_t)ti * 128 * DD;
    const __nv_bfloat16* Bhi = d_Mhi + nh * 128 * DD;
    const __nv_bfloat16* Blo = d_Mlo + nh * 128 * DD;

    for (int kc = 0; kc < 4; ++kc) {
        stage64(sm,         Ahi + kc * 64, DD, 128, tid);
        stage64(sm + 16384, Alo + kc * 64, DD, 128, tid);
        stage64(sm + 32768, Bhi + kc * 64, DD, 128, tid);
        stage64(sm + 49152, Blo + kc * 64, DD, 128, tid);
        __syncthreads();
        mma_chunk3(acc, base, base + 16384, base + 32768, base + 49152, mrow, ncol, lane);
        __syncthreads();
    }
#pragma unroll
    for (int mi = 0; mi < 2; ++mi) {
        int rA = ti * 128 + mrow + mi * 16 + (lane >> 2);
        int rB = rA + 8;
#pragma unroll
        for (int nf = 0; nf < 8; ++nf) {
            int col = nh * 128 + ncol + nf * 8 + (lane & 3) * 2;
            float h0, l0, h1, l1;
            split_hl(acc[mi][nf][0], h0, l0);
            split_hl(acc[mi][nf][1], h1, l1);
            *(uint32_t*)&d_Ghi[(size_t)rA * DD + col] = pack_bf2(h0, h1);
            *(uint32_t*)&d_Glo[(size_t)rA * DD + col] = pack_bf2(l0, l1);
            split_hl(acc[mi][nf][2], h0, l0);
            split_hl(acc[mi][nf][3], h1, l1);
            *(uint32_t*)&d_Ghi[(size_t)rB * DD + col] = pack_bf2(h0, h1);
            *(uint32_t*)&d_Glo[(size_t)rB * DD + col] = pack_bf2(l0, l1);
        }
    }
}

// ---------------------------------------------------------------------------
// K4: scores tile (nt, rt, b).  S = G @ X^T, leaky, *adj, write S + partials.
// ---------------------------------------------------------------------------
__global__ __launch_bounds__(256) void scores_kernel(const float* __restrict__ ADJ) {
    extern __shared__ __align__(128) char sm[];
    uint32_t base = smem_to_u32(sm);
    int tid = threadIdx.x, lane = tid & 31, wid = tid >> 5;
    int nt = blockIdx.x, rt = blockIdx.y, b = blockIdx.z;
    int mrow = (wid >> 1) * 32, ncol = (wid & 1) * 64;

    float acc[2][8][4];
#pragma unroll
    for (int mi = 0; mi < 2; ++mi)
#pragma unroll
        for (int nf = 0; nf < 8; ++nf)
#pragma unroll
            for (int q = 0; q < 4; ++q) acc[mi][nf][q] = 0.f;

    const __nv_bfloat16* Ahi = d_Ghi + ((size_t)b * NN + rt * 128) * DD;
    const __nv_bfloat16* Alo = d_Glo + ((size_t)b * NN + rt * 128) * DD;
    const __nv_bfloat16* Bhi = d_Xhi + ((size_t)b * NN + nt * 128) * DD;
    const __nv_bfloat16* Blo = d_Xlo + ((size_t)b * NN + nt * 128) * DD;

    for (int kc = 0; kc < 4; ++kc) {
        stage64(sm,         Ahi + kc * 64, DD, 128, tid);
        stage64(sm + 16384, Alo + kc * 64, DD, 128, tid);
        stage64(sm + 32768, Bhi + kc * 64, DD, 128, tid);
        stage64(sm + 49152, Blo + kc * 64, DD, 128, tid);
        __syncthreads();
        mma_chunk3(acc, base, base + 16384, base + 32768, base + 49152, mrow, ncol, lane);
        __syncthreads();
    }

    // epilogue: leaky -> *adj -> write S; per-(row, 64col) max & sumexp
    int cb0 = nt * 128 + ncol + (lane & 3) * 2;
    float mx[2][2] = {{-1e30f, -1e30f}, {-1e30f, -1e30f}};
#pragma unroll
    for (int mi = 0; mi < 2; ++mi) {
        int rA = rt * 128 + mrow + mi * 16 + (lane >> 2);
        int rB = rA + 8;
        const float* adjA = ADJ + ((size_t)b * NN + rA) * NN;
        const float* adjB = ADJ + ((size_t)b * NN + rB) * NN;
        float* swA = d_S + ((size_t)b * NN + rA) * NN;
        float* swB = d_S + ((size_t)b * NN + rB) * NN;
#pragma unroll
        for (int nf = 0; nf < 8; ++nf) {
            int c = cb0 + nf * 8;
            float2 aA = *(const float2*)&adjA[c];
            float2 aB = *(const float2*)&adjB[c];
            float v0 = acc[mi][nf][0]; v0 = fmaxf(v0, 0.2f * v0) * aA.x;
            float v1 = acc[mi][nf][1]; v1 = fmaxf(v1, 0.2f * v1) * aA.y;
            float v2 = acc[mi][nf][2]; v2 = fmaxf(v2, 0.2f * v2) * aB.x;
            float v3 = acc[mi][nf][3]; v3 = fmaxf(v3, 0.2f * v3) * aB.y;
            acc[mi][nf][0] = v0; acc[mi][nf][1] = v1;
            acc[mi][nf][2] = v2; acc[mi][nf][3] = v3;
            *(float2*)&swA[c] = make_float2(v0, v1);
            *(float2*)&swB[c] = make_float2(v2, v3);
            mx[mi][0] = fmaxf(mx[mi][0], fmaxf(v0, v1));
            mx[mi][1] = fmaxf(mx[mi][1], fmaxf(v2, v3));
        }
    }
#pragma unroll
    for (int mi = 0; mi < 2; ++mi)
#pragma unroll
        for (int h = 0; h < 2; ++h) {
            mx[mi][h] = fmaxf(mx[mi][h], __shfl_xor_sync(0xffffffffu, mx[mi][h], 1));
            mx[mi][h] = fmaxf(mx[mi][h], __shfl_xor_sync(0xffffffffu, mx[mi][h], 2));
        }
    float sum[2][2] = {{0.f, 0.f}, {0.f, 0.f}};
#pragma unroll
    for (int mi = 0; mi < 2; ++mi)
#pragma unroll
        for (int nf = 0; nf < 8; ++nf) {
            sum[mi][0] += __expf(acc[mi][nf][0] - mx[mi][0]) + __expf(acc[mi][nf][1] - mx[mi][0]);
            sum[mi][1] += __expf(acc[mi][nf][2] - mx[mi][1]) + __expf(acc[mi][nf][3] - mx[mi][1]);
        }
#pragma unroll
    for (int mi = 0; mi < 2; ++mi)
#pragma unroll
        for (int h = 0; h < 2; ++h) {
            sum[mi][h] += __shfl_xor_sync(0xffffffffu, sum[mi][h], 1);
            sum[mi][h] += __shfl_xor_sync(0xffffffffu, sum[mi][h], 2);
        }
    if ((lane & 3) == 0) {
        int pi = nt * 2 + (wid & 1);
#pragma unroll
        for (int mi = 0; mi < 2; ++mi)
#pragma unroll
            for (int h = 0; h < 2; ++h) {
                int row = rt * 128 + mrow + mi * 16 + (lane >> 2) + h * 8;
                size_t idx = (((size_t)b * NN + row) << 5) + pi;
                d_pm[idx] = mx[mi][h];
                d_pl[idx] = sum[mi][h];
            }
    }
}

// ---------------------------------------------------------------------------
// K5: merge partials -> d_rm, d_rl
// ---------------------------------------------------------------------------
__global__ void reduce_kernel() {
    int i = blockIdx.x * 256 + threadIdx.x;   // 0..BATCH*NN-1
    const float* pm = d_pm + ((size_t)i << 5);
    const float* pl = d_pl + ((size_t)i << 5);
    float m = -1e30f;
#pragma unroll
    for (int j = 0; j < 32; ++j) m = fmaxf(m, pm[j]);
    float l = 0.f;
#pragma unroll
    for (int j = 0; j < 32; ++j) l += pl[j] * __expf(pm[j] - m);
    d_rm[i] = m;
    d_rl[i] = l;
}

// ---------------------------------------------------------------------------
// K6: PV.  grid (dh=2, rt=16, b=16).  O = P @ X  (P on the fly from S).
// ---------------------------------------------------------------------------
__global__ __launch_bounds__(256) void pv_kernel(const float* __restrict__ bias,
                                                 float* __restrict__ OUT) {
    extern __shared__ __align__(128) char sm[];
    uint32_t base = smem_to_u32(sm);
    char* sPhi = sm;
    char* sPlo = sm + 16384;
    char* sBhi = sm + 32768;
    char* sBlo = sm + 49152;
    int tid = threadIdx.x, lane = tid & 31, wid = tid >> 5;
    int dh = blockIdx.x, rt = blockIdx.y, b = blockIdx.z;
    int mrow = (wid >> 1) * 32, ncol = (wid & 1) * 64;

    float acc[2][8][4];
#pragma unroll
    for (int mi = 0; mi < 2; ++mi)
#pragma unroll
        for (int nf = 0; nf < 8; ++nf)
#pragma unroll
            for (int q = 0; q < 4; ++q) acc[mi][nf][q] = 0.f;

    int prow = tid >> 1;
    int pc0 = (tid & 1) * 32;
    int rowg = rt * 128 + prow;
    float mr = d_rm[b * NN + rowg];
    float linv = 1.f / d_rl[b * NN + rowg];
    const float* srow = d_S + ((size_t)b * NN + rowg) * NN;
    const __nv_bfloat16* Bthi = d_Xthi + ((size_t)b * DD + dh * 128) * NN;
    const __nv_bfloat16* Btlo = d_Xtlo + ((size_t)b * DD + dh * 128) * NN;

    for (int kt = 0; kt < 32; ++kt) {           // 32 chunks of k=64
        int k0 = kt * 64;
        stage64(sBhi, Bthi + k0, NN, 128, tid);
        stage64(sBlo, Btlo + k0, NN, 128, tid);
        // generate P chunk [128 x 64] hi/lo
#pragma unroll
        for (int cc = 0; cc < 32; cc += 8) {
            float4 s0 = *(const float4*)&srow[k0 + pc0 + cc];
            float4 s1 = *(const float4*)&srow[k0 + pc0 + cc + 4];
            float p[8];
            p[0] = __expf(s0.x - mr) * linv;
            p[1] = __expf(s0.y - mr) * linv;
            p[2] = __expf(s0.z - mr) * linv;
            p[3] = __expf(s0.w - mr) * linv;
            p[4] = __expf(s1.x - mr) * linv;
            p[5] = __expf(s1.y - mr) * linv;
            p[6] = __expf(s1.z - mr) * linv;
            p[7] = __expf(s1.w - mr) * linv;
            float h[8], l[8];
#pragma unroll
            for (int q = 0; q < 8; ++q) split_hl(p[q], h[q], l[q]);
            uint32_t byte = swz((uint32_t)(prow * 128 + (pc0 + cc) * 2));
            *(uint4*)(sPhi + byte) = make_uint4(pack_bf2(h[0], h[1]), pack_bf2(h[2], h[3]),
                                                pack_bf2(h[4], h[5]), pack_bf2(h[6], h[7]));
            *(uint4*)(sPlo + byte) = make_uint4(pack_bf2(l[0], l[1]), pack_bf2(l[2], l[3]),
                                                pack_bf2(l[4], l[5]), pack_bf2(l[6], l[7]));
        }
        __syncthreads();
        mma_chunk3(acc, base, base + 16384, base + 32768, base + 49152, mrow, ncol, lane);
        __syncthreads();
    }

    // epilogue: + bias -> OUT
#pragma unroll
    for (int mi = 0; mi < 2; ++mi) {
        int rA = rt * 128 + mrow + mi * 16 + (lane >> 2);
        int rB = rA + 8;
#pragma unroll
        for (int nf = 0; nf < 8; ++nf) {
            int col = dh * 128 + ncol + nf * 8 + (lane & 3) * 2;
            float2 bv = *(const float2*)&bias[col];
            *(float2*)&OUT[((size_t)b * NN + rA) * DD + col] =
                make_float2(acc[mi][nf][0] + bv.x, acc[mi][nf][1] + bv.y);
            *(float2*)&OUT[((size_t)b * NN + rB) * DD + col] =
                make_float2(acc[mi][nf][2] + bv.x, acc[mi][nf][3] + bv.y);
        }
    }
}

// ---------------------------------------------------------------------------
extern "C" void kernel_launch(void* const* d_in, const int* in_sizes, int n_in,
                              void* d_out, int out_size) {
    const float* x    = (const float*)d_in[0];  // [16,2048,256]
    const float* adj  = (const float*)d_in[1];  // [16,2048,2048]
    const float* W    = (const float*)d_in[2];  // [256,256]
    const float* bias = (const float*)d_in[3];  // [256]
    float* out = (float*)d_out;

    wwt_kernel<<<dim3(16, 16), dim3(16, 16)>>>(W);
    convx_kernel<<<dim3(8, 64, 16), 256>>>(x);

    const int SMB = 65536;
    cudaFuncSetAttribute(gproj_kernel, cudaFuncAttributeMaxDynamicSharedMemorySize, SMB);
    cudaFuncSetAttribute(scores_kernel, cudaFuncAttributeMaxDynamicSharedMemorySize, SMB);
    cudaFuncSetAttribute(pv_kernel, cudaFuncAttributeMaxDynamicSharedMemorySize, SMB);

    gproj_kernel<<<dim3(2, 256), 256, SMB>>>();
    scores_kernel<<<dim3(16, 16, 16), 256, SMB>>>(adj);
    reduce_kernel<<<BATCH * NN / 256, 256>>>();
    pv_kernel<<<dim3(2, 16, 16), 256, SMB>>>(bias, out);
}

// round 4
// speedup vs baseline: 6.2957x; 2.3488x over previous
#include <cuda_runtime.h>
#include <cuda_bf16.h>
#include <cstdint>

#define BATCH 16
#define NN 2048
#define DD 256

// ---------------- scratch (static device globals; no allocs) ----------------
__device__ __nv_bfloat16 d_Mhi[DD * DD];
__device__ __nv_bfloat16 d_Mlo[DD * DD];
__device__ __nv_bfloat16 d_Ghi[BATCH * NN * DD];
__device__ __nv_bfloat16 d_Glo[BATCH * NN * DD];
__device__ __nv_bfloat16 d_Xhi[BATCH * NN * DD];
__device__ __nv_bfloat16 d_Xlo[BATCH * NN * DD];
__device__ __nv_bfloat16 d_Xthi[BATCH * DD * NN];
__device__ __nv_bfloat16 d_Xtlo[BATCH * DD * NN];
__device__ float d_S[(size_t)BATCH * NN * NN];            // 256 MiB scores
__device__ __nv_bfloat16 d_Phi[(size_t)BATCH * NN * NN];  // 128 MiB P hi
__device__ __nv_bfloat16 d_Plo[(size_t)BATCH * NN * NN];  // 128 MiB P lo
__device__ float d_pm[(size_t)BATCH * NN * 32];
__device__ float d_pl[(size_t)BATCH * NN * 32];
__device__ float d_rm[BATCH * NN];
__device__ float d_rl[BATCH * NN];

// ---------------- helpers ----------------
__device__ __forceinline__ uint32_t smem_to_u32(const void* p) {
    uint32_t a;
    asm("{ .reg .u64 t; cvta.to.shared.u64 t, %1; cvt.u32.u64 %0, t; }" : "=r"(a) : "l"(p));
    return a;
}
__device__ __forceinline__ void split_hl(float v, float& h, float& l) {
    __nv_bfloat16 hb = __float2bfloat16(v);
    h = __bfloat162float(hb);
    l = v - h;
}
__device__ __forceinline__ uint32_t pack_bf2(float a, float b) {
    __nv_bfloat162 h = __floats2bfloat162_rn(a, b);
    return *(uint32_t*)&h;
}
__device__ __forceinline__ void ldmx4(uint32_t (&d)[4], uint32_t addr) {
    asm volatile("ldmatrix.sync.aligned.m8n8.x4.shared.b16 {%0,%1,%2,%3}, [%4];"
                 : "=r"(d[0]), "=r"(d[1]), "=r"(d[2]), "=r"(d[3]) : "r"(addr));
}
__device__ __forceinline__ void mma16816(float (&c)[4], const uint32_t (&a)[4],
                                         uint32_t b0, uint32_t b1) {
    asm volatile(
        "mma.sync.aligned.m16n8k16.row.col.f32.bf16.bf16.f32 "
        "{%0,%1,%2,%3}, {%4,%5,%6,%7}, {%8,%9}, {%0,%1,%2,%3};"
        : "+f"(c[0]), "+f"(c[1]), "+f"(c[2]), "+f"(c[3])
        : "r"(a[0]), "r"(a[1]), "r"(a[2]), "r"(a[3]), "r"(b0), "r"(b1));
}
__device__ __forceinline__ uint32_t swz(uint32_t byte) {
    return byte ^ ((byte >> 3) & 0x70);
}
// cp.async (baseline sm_80 PTX)
__device__ __forceinline__ void cp16(uint32_t dst, const void* src) {
    asm volatile("cp.async.cg.shared.global [%0], [%1], 16;" :: "r"(dst), "l"(src));
}
#define CP_COMMIT() asm volatile("cp.async.commit_group;" ::: "memory")
#define CP_WAIT(n)  asm volatile("cp.async.wait_group %0;" :: "n"(n) : "memory")

// Stage a [128 x 64] bf16 tile (row stride = stride elems) into SW128 smem.
__device__ __forceinline__ void stage_cp(uint32_t dst, const __nv_bfloat16* src,
                                         int stride, int tid) {
#pragma unroll
    for (int p = 0; p < 4; ++p) {
        int i = tid + p * 256;
        int r = i >> 3, c = i & 7;
        cp16(dst + swz((uint32_t)(r * 128 + c * 16)), src + (size_t)r * stride + c * 8);
    }
}
// ldmatrix address: 16x16 block at (rowbase, kbyte).
__device__ __forceinline__ uint32_t tile_addr(uint32_t base, int rowbase, int kbyte, int lane) {
    int mat = lane >> 3, ri = lane & 7;
    int row = rowbase + (mat & 1) * 8 + ri;
    return base + swz((uint32_t)(row * 128 + kbyte + (mat >> 1) * 16));
}

// Warp computes 32x64 over one k=64 chunk, 3 passes (AhiBhi, AhiBlo, AloBhi).
__device__ __forceinline__ void mma_chunk3(float (&acc)[2][8][4],
                                           uint32_t aHi, uint32_t aLo,
                                           uint32_t bHi, uint32_t bLo,
                                           int mrow, int ncol, int lane) {
#pragma unroll
    for (int k16 = 0; k16 < 4; ++k16) {
        int kb = k16 * 32;
        uint32_t ah[2][4], bh[4][4];
        ldmx4(ah[0], tile_addr(aHi, mrow, kb, lane));
        ldmx4(ah[1], tile_addr(aHi, mrow + 16, kb, lane));
#pragma unroll
        for (int g = 0; g < 4; ++g) ldmx4(bh[g], tile_addr(bHi, ncol + g * 16, kb, lane));
#pragma unroll
        for (int mi = 0; mi < 2; ++mi)
#pragma unroll
            for (int g = 0; g < 4; ++g) {
                mma16816(acc[mi][g * 2 + 0], ah[mi], bh[g][0], bh[g][2]);
                mma16816(acc[mi][g * 2 + 1], ah[mi], bh[g][1], bh[g][3]);
            }
        {
            uint32_t bl[4][4];
#pragma unroll
            for (int g = 0; g < 4; ++g) ldmx4(bl[g], tile_addr(bLo, ncol + g * 16, kb, lane));
#pragma unroll
            for (int mi = 0; mi < 2; ++mi)
#pragma unroll
                for (int g = 0; g < 4; ++g) {
                    mma16816(acc[mi][g * 2 + 0], ah[mi], bl[g][0], bl[g][2]);
                    mma16816(acc[mi][g * 2 + 1], ah[mi], bl[g][1], bl[g][3]);
                }
        }
        {
            uint32_t al[2][4];
            ldmx4(al[0], tile_addr(aLo, mrow, kb, lane));
            ldmx4(al[1], tile_addr(aLo, mrow + 16, kb, lane));
#pragma unroll
            for (int mi = 0; mi < 2; ++mi)
#pragma unroll
                for (int g = 0; g < 4; ++g) {
                    mma16816(acc[mi][g * 2 + 0], al[mi], bh[g][0], bh[g][2]);
                    mma16816(acc[mi][g * 2 + 1], al[mi], bh[g][1], bh[g][3]);
                }
        }
    }
}

#define BUF 65536   // one buffer set: Ahi|Alo|Bhi|Blo, 16KB each

// ---------------------------------------------------------------------------
// K1: M = W @ W^T  -> hi/lo bf16
// ---------------------------------------------------------------------------
__global__ void wwt_kernel(const float* __restrict__ W) {
    __shared__ float sR[16][257];
    __shared__ float sC[16][257];
    int tx = threadIdx.x, ty = threadIdx.y;
    int t = ty * 16 + tx;
    int r0 = blockIdx.y * 16, c0 = blockIdx.x * 16;
    {
        int row = t >> 4, base = t & 15;
#pragma unroll
        for (int p = 0; p < 16; ++p) {
            int col = base + p * 16;
            sR[row][col] = W[(r0 + row) * DD + col];
            sC[row][col] = W[(c0 + row) * DD + col];
        }
    }
    __syncthreads();
    float acc = 0.f;
#pragma unroll 8
    for (int k = 0; k < DD; ++k) acc += sR[ty][k] * sC[tx][k];
    float h, l;
    split_hl(acc, h, l);
    d_Mhi[(r0 + ty) * DD + (c0 + tx)] = __float2bfloat16(h);
    d_Mlo[(r0 + ty) * DD + (c0 + tx)] = __float2bfloat16(l);
}

// ---------------------------------------------------------------------------
// K2: X -> Xhi/Xlo (row-major) + Xthi/Xtlo ([b][d][m])
// ---------------------------------------------------------------------------
__global__ __launch_bounds__(256) void convx_kernel(const float* __restrict__ X) {
    __shared__ float tile[32][33];
    int b = blockIdx.z;
    int m0 = blockIdx.y * 32, d0 = blockIdx.x * 32;
    int j = threadIdx.x & 31, i0 = threadIdx.x >> 5;
    const float* Xb = X + (size_t)b * NN * DD;
#pragma unroll
    for (int i = i0; i < 32; i += 8) {
        float v = Xb[(size_t)(m0 + i) * DD + d0 + j];
        tile[i][j] = v;
        float h, l;
        split_hl(v, h, l);
        size_t idx = (size_t)b * NN * DD + (size_t)(m0 + i) * DD + d0 + j;
        d_Xhi[idx] = __float2bfloat16(h);
        d_Xlo[idx] = __float2bfloat16(l);
    }
    __syncthreads();
#pragma unroll
    for (int i = i0; i < 32; i += 8) {
        float v = tile[j][i];
        float h, l;
        split_hl(v, h, l);
        size_t idx = (size_t)b * DD * NN + (size_t)(d0 + i) * NN + m0 + j;
        d_Xthi[idx] = __float2bfloat16(h);
        d_Xtlo[idx] = __float2bfloat16(l);
    }
}

// ---------------------------------------------------------------------------
// K3: G = X @ M (mma, pipelined).  grid (nh=2, tile=256).
// ---------------------------------------------------------------------------
__global__ __launch_bounds__(256) void gproj_kernel() {
    extern __shared__ __align__(128) char sm[];
    uint32_t base = smem_to_u32(sm);
    int tid = threadIdx.x, lane = tid & 31, wid = tid >> 5;
    int nh = blockIdx.x, ti = blockIdx.y;
    int mrow = (wid >> 1) * 32, ncol = (wid & 1) * 64;

    float acc[2][8][4];
#pragma unroll
    for (int mi = 0; mi < 2; ++mi)
#pragma unroll
        for (int nf = 0; nf < 8; ++nf)
#pragma unroll
            for (int q = 0; q < 4; ++q) acc[mi][nf][q] = 0.f;

    const __nv_bfloat16* Ahi = d_Xhi + (size_t)ti * 128 * DD;
    const __nv_bfloat16* Alo = d_Xlo + (size_t)ti * 128 * DD;
    const __nv_bfloat16* Bhi = d_Mhi + nh * 128 * DD;
    const __nv_bfloat16* Blo = d_Mlo + nh * 128 * DD;

    stage_cp(base, Ahi, DD, tid);
    stage_cp(base + 16384, Alo, DD, tid);
    stage_cp(base + 32768, Bhi, DD, tid);
    stage_cp(base + 49152, Blo, DD, tid);
    CP_COMMIT();

    for (int kc = 0; kc < 4; ++kc) {
        if (kc < 3) {
            uint32_t nb = base + ((kc + 1) & 1) * BUF;
            stage_cp(nb, Ahi + (kc + 1) * 64, DD, tid);
            stage_cp(nb + 16384, Alo + (kc + 1) * 64, DD, tid);
            stage_cp(nb + 32768, Bhi + (kc + 1) * 64, DD, tid);
            stage_cp(nb + 49152, Blo + (kc + 1) * 64, DD, tid);
            CP_COMMIT();
            CP_WAIT(1);
        } else {
            CP_WAIT(0);
        }
        __syncthreads();
        uint32_t cb = base + (kc & 1) * BUF;
        mma_chunk3(acc, cb, cb + 16384, cb + 32768, cb + 49152, mrow, ncol, lane);
        __syncthreads();
    }
#pragma unroll
    for (int mi = 0; mi < 2; ++mi) {
        int rA = ti * 128 + mrow + mi * 16 + (lane >> 2);
        int rB = rA + 8;
#pragma unroll
        for (int nf = 0; nf < 8; ++nf) {
            int col = nh * 128 + ncol + nf * 8 + (lane & 3) * 2;
            float h0, l0, h1, l1;
            split_hl(acc[mi][nf][0], h0, l0);
            split_hl(acc[mi][nf][1], h1, l1);
            *(uint32_t*)&d_Ghi[(size_t)rA * DD + col] = pack_bf2(h0, h1);
            *(uint32_t*)&d_Glo[(size_t)rA * DD + col] = pack_bf2(l0, l1);
            split_hl(acc[mi][nf][2], h0, l0);
            split_hl(acc[mi][nf][3], h1, l1);
            *(uint32_t*)&d_Ghi[(size_t)rB * DD + col] = pack_bf2(h0, h1);
            *(uint32_t*)&d_Glo[(size_t)rB * DD + col] = pack_bf2(l0, l1);
        }
    }
}

// ---------------------------------------------------------------------------
// K4: scores tile (nt, rt, b), pipelined.
// ---------------------------------------------------------------------------
__global__ __launch_bounds__(256) void scores_kernel(const float* __restrict__ ADJ) {
    extern __shared__ __align__(128) char sm[];
    uint32_t base = smem_to_u32(sm);
    int tid = threadIdx.x, lane = tid & 31, wid = tid >> 5;
    int nt = blockIdx.x, rt = blockIdx.y, b = blockIdx.z;
    int mrow = (wid >> 1) * 32, ncol = (wid & 1) * 64;

    float acc[2][8][4];
#pragma unroll
    for (int mi = 0; mi < 2; ++mi)
#pragma unroll
        for (int nf = 0; nf < 8; ++nf)
#pragma unroll
            for (int q = 0; q < 4; ++q) acc[mi][nf][q] = 0.f;

    const __nv_bfloat16* Ahi = d_Ghi + ((size_t)b * NN + rt * 128) * DD;
    const __nv_bfloat16* Alo = d_Glo + ((size_t)b * NN + rt * 128) * DD;
    const __nv_bfloat16* Bhi = d_Xhi + ((size_t)b * NN + nt * 128) * DD;
    const __nv_bfloat16* Blo = d_Xlo + ((size_t)b * NN + nt * 128) * DD;

    stage_cp(base, Ahi, DD, tid);
    stage_cp(base + 16384, Alo, DD, tid);
    stage_cp(base + 32768, Bhi, DD, tid);
    stage_cp(base + 49152, Blo, DD, tid);
    CP_COMMIT();

    for (int kc = 0; kc < 4; ++kc) {
        if (kc < 3) {
            uint32_t nb = base + ((kc + 1) & 1) * BUF;
            stage_cp(nb, Ahi + (kc + 1) * 64, DD, tid);
            stage_cp(nb + 16384, Alo + (kc + 1) * 64, DD, tid);
            stage_cp(nb + 32768, Bhi + (kc + 1) * 64, DD, tid);
            stage_cp(nb + 49152, Blo + (kc + 1) * 64, DD, tid);
            CP_COMMIT();
            CP_WAIT(1);
        } else {
            CP_WAIT(0);
        }
        __syncthreads();
        uint32_t cb = base + (kc & 1) * BUF;
        mma_chunk3(acc, cb, cb + 16384, cb + 32768, cb + 49152, mrow, ncol, lane);
        __syncthreads();
    }

    // epilogue: leaky -> *adj -> write S; per-(row, 64col) max & sumexp
    int cb0 = nt * 128 + ncol + (lane & 3) * 2;
    float mx[2][2] = {{-1e30f, -1e30f}, {-1e30f, -1e30f}};
#pragma unroll
    for (int mi = 0; mi < 2; ++mi) {
        int rA = rt * 128 + mrow + mi * 16 + (lane >> 2);
        int rB = rA + 8;
        const float* adjA = ADJ + ((size_t)b * NN + rA) * NN;
        const float* adjB = ADJ + ((size_t)b * NN + rB) * NN;
        float* swA = d_S + ((size_t)b * NN + rA) * NN;
        float* swB = d_S + ((size_t)b * NN + rB) * NN;
#pragma unroll
        for (int nf = 0; nf < 8; ++nf) {
            int c = cb0 + nf * 8;
            float2 aA = *(const float2*)&adjA[c];
            float2 aB = *(const float2*)&adjB[c];
            float v0 = acc[mi][nf][0]; v0 = fmaxf(v0, 0.2f * v0) * aA.x;
            float v1 = acc[mi][nf][1]; v1 = fmaxf(v1, 0.2f * v1) * aA.y;
            float v2 = acc[mi][nf][2]; v2 = fmaxf(v2, 0.2f * v2) * aB.x;
            float v3 = acc[mi][nf][3]; v3 = fmaxf(v3, 0.2f * v3) * aB.y;
            acc[mi][nf][0] = v0; acc[mi][nf][1] = v1;
            acc[mi][nf][2] = v2; acc[mi][nf][3] = v3;
            *(float2*)&swA[c] = make_float2(v0, v1);
            *(float2*)&swB[c] = make_float2(v2, v3);
            mx[mi][0] = fmaxf(mx[mi][0], fmaxf(v0, v1));
            mx[mi][1] = fmaxf(mx[mi][1], fmaxf(v2, v3));
        }
    }
#pragma unroll
    for (int mi = 0; mi < 2; ++mi)
#pragma unroll
        for (int h = 0; h < 2; ++h) {
            mx[mi][h] = fmaxf(mx[mi][h], __shfl_xor_sync(0xffffffffu, mx[mi][h], 1));
            mx[mi][h] = fmaxf(mx[mi][h], __shfl_xor_sync(0xffffffffu, mx[mi][h], 2));
        }
    float sum[2][2] = {{0.f, 0.f}, {0.f, 0.f}};
#pragma unroll
    for (int mi = 0; mi < 2; ++mi)
#pragma unroll
        for (int nf = 0; nf < 8; ++nf) {
            sum[mi][0] += __expf(acc[mi][nf][0] - mx[mi][0]) + __expf(acc[mi][nf][1] - mx[mi][0]);
            sum[mi][1] += __expf(acc[mi][nf][2] - mx[mi][1]) + __expf(acc[mi][nf][3] - mx[mi][1]);
        }
#pragma unroll
    for (int mi = 0; mi < 2; ++mi)
#pragma unroll
        for (int h = 0; h < 2; ++h) {
            sum[mi][h] += __shfl_xor_sync(0xffffffffu, sum[mi][h], 1);
            sum[mi][h] += __shfl_xor_sync(0xffffffffu, sum[mi][h], 2);
        }
    if ((lane & 3) == 0) {
        int pi = nt * 2 + (wid & 1);
#pragma unroll
        for (int mi = 0; mi < 2; ++mi)
#pragma unroll
            for (int h = 0; h < 2; ++h) {
                int row = rt * 128 + mrow + mi * 16 + (lane >> 2) + h * 8;
                size_t idx = (((size_t)b * NN + row) << 5) + pi;
                d_pm[idx] = mx[mi][h];
                d_pl[idx] = sum[mi][h];
            }
    }
}

// ---------------------------------------------------------------------------
// K5: merge partials -> d_rm, d_rl
// ---------------------------------------------------------------------------
__global__ void reduce_kernel() {
    int i = blockIdx.x * 256 + threadIdx.x;
    const float* pm = d_pm + ((size_t)i << 5);
    const float* pl = d_pl + ((size_t)i << 5);
    float m = -1e30f;
#pragma unroll
    for (int j = 0; j < 32; ++j) m = fmaxf(m, pm[j]);
    float l = 0.f;
#pragma unroll
    for (int j = 0; j < 32; ++j) l += pl[j] * __expf(pm[j] - m);
    d_rm[i] = m;
    d_rl[i] = l;
}

// ---------------------------------------------------------------------------
// K6: S -> P hi/lo bf16  (p = exp(s - m) / l)
// ---------------------------------------------------------------------------
__global__ __launch_bounds__(256) void expp_kernel() {
    size_t i = ((size_t)blockIdx.x * 256 + threadIdx.x) * 8;
    int row = (int)(i >> 11);     // global row b*NN+n
    float m = d_rm[row];
    float linv = 1.f / d_rl[row];
    float4 s0 = *(const float4*)&d_S[i];
    float4 s1 = *(const float4*)&d_S[i + 4];
    float p[8];
    p[0] = __expf(s0.x - m) * linv;
    p[1] = __expf(s0.y - m) * linv;
    p[2] = __expf(s0.z - m) * linv;
    p[3] = __expf(s0.w - m) * linv;
    p[4] = __expf(s1.x - m) * linv;
    p[5] = __expf(s1.y - m) * linv;
    p[6] = __expf(s1.z - m) * linv;
    p[7] = __expf(s1.w - m) * linv;
    float h[8], l[8];
#pragma unroll
    for (int q = 0; q < 8; ++q) split_hl(p[q], h[q], l[q]);
    *(uint4*)&d_Phi[i] = make_uint4(pack_bf2(h[0], h[1]), pack_bf2(h[2], h[3]),
                                    pack_bf2(h[4], h[5]), pack_bf2(h[6], h[7]));
    *(uint4*)&d_Plo[i] = make_uint4(pack_bf2(l[0], l[1]), pack_bf2(l[2], l[3]),
                                    pack_bf2(l[4], l[5]), pack_bf2(l[6], l[7]));
}

// ---------------------------------------------------------------------------
// K7: PV, pipelined.  grid (dh=2, rt=16, b=16).  O = P @ Xt^T.
// ---------------------------------------------------------------------------
__global__ __launch_bounds__(256) void pv_kernel(const float* __restrict__ bias,
                                                 float* __restrict__ OUT) {
    extern __shared__ __align__(128) char sm[];
    uint32_t base = smem_to_u32(sm);
    int tid = threadIdx.x, lane = tid & 31, wid = tid >> 5;
    int dh = blockIdx.x, rt = blockIdx.y, b = blockIdx.z;
    int mrow = (wid >> 1) * 32, ncol = (wid & 1) * 64;

    float acc[2][8][4];
#pragma unroll
    for (int mi = 0; mi < 2; ++mi)
#pragma unroll
        for (int nf = 0; nf < 8; ++nf)
#pragma unroll
            for (int q = 0; q < 4; ++q) acc[mi][nf][q] = 0.f;

    const __nv_bfloat16* Phi = d_Phi + ((size_t)b * NN + rt * 128) * NN;
    const __nv_bfloat16* Plo = d_Plo + ((size_t)b * NN + rt * 128) * NN;
    const __nv_bfloat16* Bthi = d_Xthi + ((size_t)b * DD + dh * 128) * NN;
    const __nv_bfloat16* Btlo = d_Xtlo + ((size_t)b * DD + dh * 128) * NN;

    stage_cp(base, Phi, NN, tid);
    stage_cp(base + 16384, Plo, NN, tid);
    stage_cp(base + 32768, Bthi, NN, tid);
    stage_cp(base + 49152, Btlo, NN, tid);
    CP_COMMIT();

    for (int kt = 0; kt < 32; ++kt) {
        if (kt < 31) {
            uint32_t nb = base + ((kt + 1) & 1) * BUF;
            int k0 = (kt + 1) * 64;
            stage_cp(nb, Phi + k0, NN, tid);
            stage_cp(nb + 16384, Plo + k0, NN, tid);
            stage_cp(nb + 32768, Bthi + k0, NN, tid);
            stage_cp(nb + 49152, Btlo + k0, NN, tid);
            CP_COMMIT();
            CP_WAIT(1);
        } else {
            CP_WAIT(0);
        }
        __syncthreads();
        uint32_t cb = base + (kt & 1) * BUF;
        mma_chunk3(acc, cb, cb + 16384, cb + 32768, cb + 49152, mrow, ncol, lane);
        __syncthreads();
    }

#pragma unroll
    for (int mi = 0; mi < 2; ++mi) {
        int rA = rt * 128 + mrow + mi * 16 + (lane >> 2);
        int rB = rA + 8;
#pragma unroll
        for (int nf = 0; nf < 8; ++nf) {
            int col = dh * 128 + ncol + nf * 8 + (lane & 3) * 2;
            float2 bv = *(const float2*)&bias[col];
            *(float2*)&OUT[((size_t)b * NN + rA) * DD + col] =
                make_float2(acc[mi][nf][0] + bv.x, acc[mi][nf][1] + bv.y);
            *(float2*)&OUT[((size_t)b * NN + rB) * DD + col] =
                make_float2(acc[mi][nf][2] + bv.x, acc[mi][nf][3] + bv.y);
        }
    }
}

// ---------------------------------------------------------------------------
extern "C" void kernel_launch(void* const* d_in, const int* in_sizes, int n_in,
                              void* d_out, int out_size) {
    const float* x    = (const float*)d_in[0];
    const float* adj  = (const float*)d_in[1];
    const float* W    = (const float*)d_in[2];
    const float* bias = (const float*)d_in[3];
    float* out = (float*)d_out;

    wwt_kernel<<<dim3(16, 16), dim3(16, 16)>>>(W);
    convx_kernel<<<dim3(8, 64, 16), 256>>>(x);

    const int SMB = 2 * BUF;   // 128 KB
    cudaFuncSetAttribute(gproj_kernel, cudaFuncAttributeMaxDynamicSharedMemorySize, SMB);
    cudaFuncSetAttribute(scores_kernel, cudaFuncAttributeMaxDynamicSharedMemorySize, SMB);
    cudaFuncSetAttribute(pv_kernel, cudaFuncAttributeMaxDynamicSharedMemorySize, SMB);

    gproj_kernel<<<dim3(2, 256), 256, SMB>>>();
    scores_kernel<<<dim3(16, 16, 16), 256, SMB>>>(adj);
    reduce_kernel<<<BATCH * NN / 256, 256>>>();
    expp_kernel<<<(int)((size_t)BATCH * NN * NN / 2048), 256>>>();
    pv_kernel<<<dim3(2, 16, 16), 256, SMB>>>(bias, out);
}